// round 13
// baseline (speedup 1.0000x reference)
#include <cuda_runtime.h>
#include <cstdint>
#include <cstddef>

#define LSEQ   2048
#define HEADS  16
#define DHEAD  64
#define DMODEL 1024
#define MROWS  4096
#define BH     32

typedef unsigned short u16;   // bf16 bit pattern

// ---------------- 64 MiB aliased pool (empirical cap: 64 MiB passes, 96 trips)
#define POOL_ELEMS (32u * 1024u * 1024u)
__device__ __align__(256) u16 g_pool[POOL_ELEMS];

#define O_QH   (0ul)
#define O_QL   (4ul  << 20)
#define O_KH   (8ul  << 20)
#define O_KL   (12ul << 20)
#define O_VTH  (16ul << 20)
#define O_VTL  (20ul << 20)
#define O_WQKH (24ul << 20)
#define O_WQKL (26ul << 20)
#define O_WVH  (28ul << 20)
#define O_WVL  (29ul << 20)
#define O_YH   (24ul << 20)
#define O_YL   (28ul << 20)
#define O_WOH  (0ul)
#define O_WOL  (1ul << 20)

// ---------------- helpers --------------------------------------------------
__device__ __forceinline__ uint32_t smem_u32(const void* p) {
    uint32_t a;
    asm("{ .reg .u64 t; cvta.to.shared.u64 t, %1; cvt.u32.u64 %0, t; }" : "=r"(a) : "l"(p));
    return a;
}

#define LDSM4(r0, r1, r2, r3, addr) \
    asm volatile("ldmatrix.sync.aligned.m8n8.x4.shared.b16 {%0,%1,%2,%3}, [%4];" \
        : "=r"(r0), "=r"(r1), "=r"(r2), "=r"(r3) : "r"(addr))

#define LDSM4T(r0, r1, r2, r3, addr) \
    asm volatile("ldmatrix.sync.aligned.m8n8.x4.trans.shared.b16 {%0,%1,%2,%3}, [%4];" \
        : "=r"(r0), "=r"(r1), "=r"(r2), "=r"(r3) : "r"(addr))

#define MMA4(c0, c1, c2, c3, a0, a1, a2, a3, b0, b1) \
    asm volatile("mma.sync.aligned.m16n8k16.row.col.f32.bf16.bf16.f32 " \
        "{%0,%1,%2,%3}, {%4,%5,%6,%7}, {%8,%9}, {%0,%1,%2,%3};" \
        : "+f"(c0), "+f"(c1), "+f"(c2), "+f"(c3) \
        : "r"(a0), "r"(a1), "r"(a2), "r"(a3), "r"(b0), "r"(b1))

__device__ __forceinline__ void cpasync16(uint32_t dst, const void* src) {
    asm volatile("cp.async.cg.shared.global [%0], [%1], 16;" :: "r"(dst), "l"(src));
}
#define CP_COMMIT() asm volatile("cp.async.commit_group;" ::: "memory")
#define CP_WAIT(n)  asm volatile("cp.async.wait_group %0;" :: "n"(n) : "memory")

__device__ __forceinline__ float fast_exp(float x) {
    float y = x * 1.4426950408889634f;
    float z = y + 12582912.0f;
    int   n = __float_as_int(z) - 0x4B400000;
    float f = y - (z - 12582912.0f);
    float p = 1.3333558146e-3f;
    p = fmaf(p, f, 9.6181291076e-3f);
    p = fmaf(p, f, 5.5504108665e-2f);
    p = fmaf(p, f, 2.4022650696e-1f);
    p = fmaf(p, f, 6.9314718056e-1f);
    p = fmaf(p, f, 1.0f);
    return __int_as_float(__float_as_int(p) + (n << 23));
}
__device__ __forceinline__ uint32_t pack2(float a, float b) {
    uint32_t r;
    asm("cvt.rn.bf16x2.f32 %0, %1, %2;" : "=r"(r) : "f"(b), "f"(a));
    return r;
}
__device__ __forceinline__ float bf16_rn(float v) {
    uint32_t u = __float_as_uint(v);
    return __uint_as_float((u + 0x7FFFu + ((u >> 16) & 1u)) & 0xFFFF0000u);
}
__device__ __forceinline__ void bsplit(float v, float& hi, float& lo) {
    hi = bf16_rn(v);
    lo = v - hi;
}
__device__ __forceinline__ u16 bf16_bits(float v_already_rounded) {
    return (u16)(__float_as_uint(v_already_rounded) >> 16);
}

// ---------------------------------------------------------------------------
// weight splitter: fp32 [n] -> hi/lo bf16 at pool offsets
// ---------------------------------------------------------------------------
__global__ void k_wsplit(const float* __restrict__ s, size_t offh, size_t offl, int n4)
{
    int i = blockIdx.x * blockDim.x + threadIdx.x;
    if (i >= n4) return;
    float4 v = ((const float4*)s)[i];
    float h0, l0, h1, l1, h2, l2, h3, l3;
    bsplit(v.x, h0, l0); bsplit(v.y, h1, l1); bsplit(v.z, h2, l2); bsplit(v.w, h3, l3);
    uint2 uh, ul;
    uh.x = pack2(h0, h1); uh.y = pack2(h2, h3);
    ul.x = pack2(l0, l1); ul.y = pack2(l2, l3);
    ((uint2*)(g_pool + offh))[i] = uh;
    ((uint2*)(g_pool + offl))[i] = ul;
}

// ===========================================================================
// Projections: 512 threads / 16 warps, C tile 128x128, warp tile 32x32.
// Single __syncthreads per K-chunk; A double-buffered (in-kernel split),
// B 4-slot cp.async ring with prefetch depth 3.
// A buffer: hi[128x80B] + lo at +10240, ABUF=20480, 2 buffers.
// B slot:   hi 32x272B rows (8704) + lo at +8704, BSTRIDE=17408, 4 slots.
// ===========================================================================
#define ABUF     20480
#define OFF_AL   10240
#define OFF_B    40960
#define BSTRIDE  17408
#define BLO      8704
#define PROJ_SMEM 110592           /* 2*20480 + 4*17408 */
#define KV_SMEM   110592
#define OUT_BBASE 81920            /* A ring 4*20480, then B ring */
#define KOUT_SMEM 151552

// truncation split + prmt packing: hi = bit-truncated bf16, lo = RN(residual)
#define CVT8T_STS(dsthi, dstlo, va, vb)                                       \
    {                                                                         \
        uint32_t _u0=__float_as_uint((va).x), _u1=__float_as_uint((va).y),    \
                 _u2=__float_as_uint((va).z), _u3=__float_as_uint((va).w),    \
                 _u4=__float_as_uint((vb).x), _u5=__float_as_uint((vb).y),    \
                 _u6=__float_as_uint((vb).z), _u7=__float_as_uint((vb).w);    \
        uint4 _uh;                                                            \
        asm("prmt.b32 %0, %1, %2, 0x7632;" : "=r"(_uh.x) : "r"(_u0), "r"(_u1)); \
        asm("prmt.b32 %0, %1, %2, 0x7632;" : "=r"(_uh.y) : "r"(_u2), "r"(_u3)); \
        asm("prmt.b32 %0, %1, %2, 0x7632;" : "=r"(_uh.z) : "r"(_u4), "r"(_u5)); \
        asm("prmt.b32 %0, %1, %2, 0x7632;" : "=r"(_uh.w) : "r"(_u6), "r"(_u7)); \
        float _l0=(va).x-__uint_as_float(_u0&0xFFFF0000u);                    \
        float _l1=(va).y-__uint_as_float(_u1&0xFFFF0000u);                    \
        float _l2=(va).z-__uint_as_float(_u2&0xFFFF0000u);                    \
        float _l3=(va).w-__uint_as_float(_u3&0xFFFF0000u);                    \
        float _l4=(vb).x-__uint_as_float(_u4&0xFFFF0000u);                    \
        float _l5=(vb).y-__uint_as_float(_u5&0xFFFF0000u);                    \
        float _l6=(vb).z-__uint_as_float(_u6&0xFFFF0000u);                    \
        float _l7=(vb).w-__uint_as_float(_u7&0xFFFF0000u);                    \
        uint4 _ul;                                                            \
        _ul.x = pack2(_l0,_l1); _ul.y = pack2(_l2,_l3);                       \
        _ul.z = pack2(_l4,_l5); _ul.w = pack2(_l6,_l7);                       \
        *(uint4*)(dsthi) = _uh;                                               \
        *(uint4*)(dstlo) = _ul;                                               \
    }

// one B chunk (hi+lo): 512 threads x 16B covers 32x128 u16 per half
#define CPB(KCN, DB)                                                          \
    {                                                                         \
        const u16* _sh = srcBH + (size_t)(KCN) * 32 * LDBv;                   \
        const u16* _sl = srcBL + (size_t)(KCN) * 32 * LDBv;                   \
        cpasync16((DB), _sh);                                                 \
        cpasync16((DB) + BLO, _sl);                                           \
    }

// MMA phase: warp tile 32x32, ks in {0,1}, np in {0,1}
#define PROJ_MMA_PHASE(AB0, ALO2, BB)                                         \
    _Pragma("unroll")                                                         \
    for (int ks = 0; ks < 2; ++ks) {                                          \
        uint32_t ah[2][4], al[2][4];                                          \
        _Pragma("unroll")                                                     \
        for (int i = 0; i < 2; ++i) {                                         \
            int row = wm * 32 + i * 16 + (lane & 15);                         \
            uint32_t a = (AB0) + row * 80 + (ks * 2 + (lane >> 4)) * 16;      \
            LDSM4(ah[i][0], ah[i][1], ah[i][2], ah[i][3], a);                 \
            LDSM4(al[i][0], al[i][1], al[i][2], al[i][3], a + (ALO2));        \
        }                                                                     \
        _Pragma("unroll")                                                     \
        for (int np = 0; np < 2; ++np) {                                      \
            int tilei = lane >> 3;                                            \
            int krow = ks * 16 + (tilei & 1) * 8 + (lane & 7);                \
            int ncol = wn * 32 + np * 16 + (tilei >> 1) * 8;                  \
            uint32_t a = (BB) + krow * 272 + ncol * 2;                        \
            uint32_t b0, b1, b2, b3, c0, c1, c2, c3;                          \
            LDSM4T(b0, b1, b2, b3, a);                                        \
            LDSM4T(c0, c1, c2, c3, a + BLO);                                  \
            _Pragma("unroll")                                                 \
            for (int i = 0; i < 2; ++i) {                                     \
                MMA4(acc[i][2*np][0], acc[i][2*np][1],                        \
                     acc[i][2*np][2], acc[i][2*np][3],                        \
                     ah[i][0], ah[i][1], ah[i][2], ah[i][3], b0, b1);         \
                MMA4(acc[i][2*np][0], acc[i][2*np][1],                        \
                     acc[i][2*np][2], acc[i][2*np][3],                        \
                     al[i][0], al[i][1], al[i][2], al[i][3], b0, b1);         \
                MMA4(acc[i][2*np][0], acc[i][2*np][1],                        \
                     acc[i][2*np][2], acc[i][2*np][3],                        \
                     ah[i][0], ah[i][1], ah[i][2], ah[i][3], c0, c1);         \
                MMA4(acc[i][2*np+1][0], acc[i][2*np+1][1],                    \
                     acc[i][2*np+1][2], acc[i][2*np+1][3],                    \
                     ah[i][0], ah[i][1], ah[i][2], ah[i][3], b2, b3);         \
                MMA4(acc[i][2*np+1][0], acc[i][2*np+1][1],                    \
                     acc[i][2*np+1][2], acc[i][2*np+1][3],                    \
                     al[i][0], al[i][1], al[i][2], al[i][3], b2, b3);         \
                MMA4(acc[i][2*np+1][0], acc[i][2*np+1][1],                    \
                     acc[i][2*np+1][2], acc[i][2*np+1][3],                    \
                     ah[i][0], ah[i][1], ah[i][2], ah[i][3], c2, c3);         \
            }                                                                 \
        }                                                                     \
    }

// Projection with fp32 A (split in-kernel, double-buffered) + pre-split B
// (4-slot cp.async ring). ONE __syncthreads per K-chunk.
#define PROJ_BODY_AF32(APTR, WHOFF, WLOFF, LDB, N0)                           \
{                                                                             \
    const int r_a = tid >> 2;                                                 \
    const int kb = tid >> 4, nq = tid & 15;                                   \
    const int LDBv = (LDB);                                                   \
    const float* gA = (APTR) + (size_t)r_a * DMODEL + (tid & 3) * 8;          \
    const u16* srcBH = g_pool + (WHOFF) + (size_t)kb * LDBv + (N0) + nq * 8;  \
    const u16* srcBL = g_pool + (WLOFF) + (size_t)kb * LDBv + (N0) + nq * 8;  \
    const uint32_t dBb = sb + OFF_B + kb * 272 + nq * 16;                     \
    CPB(0, dBb + 0 * BSTRIDE); CP_COMMIT();                                   \
    CPB(1, dBb + 1 * BSTRIDE); CP_COMMIT();                                   \
    CPB(2, dBb + 2 * BSTRIDE); CP_COMMIT();                                   \
    char* aHbase = cb + r_a * 80 + (tid & 3) * 16;                            \
    float4 pa0 = *(const float4*)gA, pa1 = *(const float4*)(gA + 4);          \
    CVT8T_STS(aHbase, aHbase + OFF_AL, pa0, pa1);     /* chunk 0 -> bufA0 */  \
    gA += 32;                                                                 \
    pa0 = *(const float4*)gA; pa1 = *(const float4*)(gA + 4);  /* chunk 1 */  \
    _Pragma("unroll 1")                                                       \
    for (int kc = 0; kc < 32; ++kc) {                                         \
        if (kc < 30) CP_WAIT(2); else if (kc == 30) CP_WAIT(1); else CP_WAIT(0); \
        __syncthreads();                                                      \
        if (kc < 31) {                                                        \
            char* aD = aHbase + ((kc + 1) & 1) * ABUF;                        \
            CVT8T_STS(aD, aD + OFF_AL, pa0, pa1);                             \
        }                                                                     \
        if (kc < 30) {                                                        \
            gA += 32;                                                         \
            pa0 = *(const float4*)gA; pa1 = *(const float4*)(gA + 4);         \
        }                                                                     \
        if (kc <= 28) { CPB(kc + 3, dBb + ((kc + 3) & 3) * BSTRIDE); CP_COMMIT(); } \
        const uint32_t aB = sb + (kc & 1) * ABUF;                             \
        const uint32_t bB = sb + OFF_B + (kc & 3) * BSTRIDE;                  \
        PROJ_MMA_PHASE(aB, OFF_AL, bB)                                        \
    }                                                                         \
}

#define PROJ_PROLOGUE()                                                       \
    extern __shared__ char cb[];                                              \
    const uint32_t sb = smem_u32(cb);                                         \
    const int tid = threadIdx.x, lane = tid & 31, wid = tid >> 5;             \
    const int wm = wid & 3, wn = wid >> 2;                                    \
    float acc[2][4][4];                                                       \
    _Pragma("unroll")                                                         \
    for (int i = 0; i < 2; ++i)                                               \
        _Pragma("unroll")                                                     \
        for (int j = 0; j < 4; ++j)                                           \
            _Pragma("unroll")                                                 \
            for (int c = 0; c < 4; ++c) acc[i][j][c] = 0.f;

// ---------------------------------------------------------------------------
// QK projection + per-head LayerNorm. grid (16 heads, 32 mtiles), 512 thr.
// Warp pair (wn, wn^1) shares each 64-dim LN row: cross-warp smem reduction.
// ---------------------------------------------------------------------------
__global__ __launch_bounds__(512, 1) void k_qk_ln(
    const float* __restrict__ X,
    const float* __restrict__ qsc, const float* __restrict__ qbi,
    const float* __restrict__ ksc, const float* __restrict__ kbi)
{
    PROJ_PROLOGUE();
    const int h = blockIdx.x, row0 = blockIdx.y * 128;
    PROJ_BODY_AF32(X + (size_t)row0 * DMODEL, O_WQKH, O_WQKL, 2048, h * 128);

    const int g = lane >> 2, tg = lane & 3;
    const int isK = wn >> 1;           // wn 0,1 -> q half; 2,3 -> k half
    const int colbase = (wn & 1) * 32; // within the 64-dim half
    const float* sc = isK ? ksc : qsc;
    const float* bi = isK ? kbi : qbi;
    u16* dh = g_pool + (isK ? O_KH : O_QH);
    u16* dl = g_pool + (isK ? O_KL : O_QL);

    float* Ss = (float*)cb;        // [4 wn][128 rows]
    float* Sq = Ss + 512;
    __syncthreads();               // all MMA reads done; smem reusable

    float ps[2][4];
    #pragma unroll
    for (int i = 0; i < 2; ++i) {
        float s0 = 0.f, s1 = 0.f, q0 = 0.f, q1 = 0.f;
        #pragma unroll
        for (int j = 0; j < 4; ++j) {
            #pragma unroll
            for (int c = 0; c < 4; ++c) acc[i][j][c] *= 0.03125f;
            s0 += acc[i][j][0] + acc[i][j][1];
            s1 += acc[i][j][2] + acc[i][j][3];
            q0 += acc[i][j][0] * acc[i][j][0] + acc[i][j][1] * acc[i][j][1];
            q1 += acc[i][j][2] * acc[i][j][2] + acc[i][j][3] * acc[i][j][3];
        }
        #pragma unroll
        for (int m = 1; m < 4; m <<= 1) {
            s0 += __shfl_xor_sync(0xffffffffu, s0, m);
            s1 += __shfl_xor_sync(0xffffffffu, s1, m);
            q0 += __shfl_xor_sync(0xffffffffu, q0, m);
            q1 += __shfl_xor_sync(0xffffffffu, q1, m);
        }
        ps[i][0] = s0; ps[i][1] = s1; ps[i][2] = q0; ps[i][3] = q1;
        if (tg == 0) {
            int r0 = wm * 32 + i * 16 + g;
            Ss[wn * 128 + r0]     = s0;
            Ss[wn * 128 + r0 + 8] = s1;
            Sq[wn * 128 + r0]     = q0;
            Sq[wn * 128 + r0 + 8] = q1;
        }
    }
    __syncthreads();

    #pragma unroll
    for (int i = 0; i < 2; ++i) {
        int r0 = wm * 32 + i * 16 + g;
        float s0 = ps[i][0] + Ss[(wn ^ 1) * 128 + r0];
        float s1 = ps[i][1] + Ss[(wn ^ 1) * 128 + r0 + 8];
        float q0 = ps[i][2] + Sq[(wn ^ 1) * 128 + r0];
        float q1 = ps[i][3] + Sq[(wn ^ 1) * 128 + r0 + 8];
        float mu0 = s0 * (1.f / 64.f), mu1 = s1 * (1.f / 64.f);
        float iv0 = rsqrtf(q0 * (1.f / 64.f) - mu0 * mu0 + 1e-6f);
        float iv1 = rsqrtf(q1 * (1.f / 64.f) - mu1 * mu1 + 1e-6f);

        int m = row0 + r0;
        int b = m >> 11, l = m & (LSEQ - 1);
        size_t base0 = ((size_t)(b * HEADS + h) * LSEQ + l) * DHEAD;
        size_t base1 = base0 + 8 * DHEAD;

        #pragma unroll
        for (int j = 0; j < 4; ++j) {
            int col = colbase + j * 8 + 2 * tg;
            float sc0 = sc[col], sc1 = sc[col + 1], bi0 = bi[col], bi1 = bi[col + 1];
            float y0 = (acc[i][j][0] - mu0) * iv0 * sc0 + bi0;
            float y1 = (acc[i][j][1] - mu0) * iv0 * sc1 + bi1;
            float y2 = (acc[i][j][2] - mu1) * iv1 * sc0 + bi0;
            float y3 = (acc[i][j][3] - mu1) * iv1 * sc1 + bi1;
            float h0, l0, h1, l1, h2, l2, h3, l3;
            bsplit(y0, h0, l0); bsplit(y1, h1, l1); bsplit(y2, h2, l2); bsplit(y3, h3, l3);
            *(uint32_t*)(dh + base0 + col) = pack2(h0, h1);
            *(uint32_t*)(dl + base0 + col) = pack2(l0, l1);
            *(uint32_t*)(dh + base1 + col) = pack2(h2, h3);
            *(uint32_t*)(dl + base1 + col) = pack2(l2, l3);
        }
    }
}

// ---------------------------------------------------------------------------
// V projection -> transposed Vt [bh][d][l] (smem transpose). grid (8, 32), 512 thr
// ---------------------------------------------------------------------------
__global__ __launch_bounds__(512, 1) void k_v(const float* __restrict__ X)
{
    PROJ_PROLOGUE();
    const int n0b = blockIdx.x * 128, row0 = blockIdx.y * 128;
    PROJ_BODY_AF32(X + (size_t)row0 * DMODEL, O_WVH, O_WVL, 1024, n0b);

    u16* Th = (u16*)cb;                 // [128 n][136 m]
    u16* Tl = Th + 128 * 136;
    const int g = lane >> 2, tg = lane & 3;
    __syncthreads();

    #pragma unroll
    for (int i = 0; i < 2; ++i) {
        int r0 = wm * 32 + i * 16 + g;
        #pragma unroll
        for (int j = 0; j < 4; ++j) {
            int n = wn * 32 + j * 8 + 2 * tg;
            float h0, l0, h1, l1, h2, l2, h3, l3;
            bsplit(acc[i][j][0] * 0.03125f, h0, l0);
            bsplit(acc[i][j][1] * 0.03125f, h1, l1);
            bsplit(acc[i][j][2] * 0.03125f, h2, l2);
            bsplit(acc[i][j][3] * 0.03125f, h3, l3);
            Th[n * 136 + r0]           = bf16_bits(h0);
            Th[(n + 1) * 136 + r0]     = bf16_bits(h1);
            Th[n * 136 + r0 + 8]       = bf16_bits(h2);
            Th[(n + 1) * 136 + r0 + 8] = bf16_bits(h3);
            Tl[n * 136 + r0]           = bf16_bits(bf16_rn(l0));
            Tl[(n + 1) * 136 + r0]     = bf16_bits(bf16_rn(l1));
            Tl[n * 136 + r0 + 8]       = bf16_bits(bf16_rn(l2));
            Tl[(n + 1) * 136 + r0 + 8] = bf16_bits(bf16_rn(l3));
        }
    }
    __syncthreads();

    const int n = tid >> 2, mh = (tid & 3) * 32;
    const int ng = n0b + n, hh = ng >> 6, d = ng & 63;
    const int b = row0 >> 11, l0 = row0 & (LSEQ - 1);
    u16* dsth = g_pool + O_VTH + ((size_t)(b * HEADS + hh) * DHEAD + d) * LSEQ + l0 + mh;
    u16* dstl = g_pool + O_VTL + ((size_t)(b * HEADS + hh) * DHEAD + d) * LSEQ + l0 + mh;
    #pragma unroll
    for (int u = 0; u < 4; ++u) {
        *(uint4*)(dsth + u * 8) = *(uint4*)(Th + n * 136 + mh + u * 8);
        *(uint4*)(dstl + u * 8) = *(uint4*)(Tl + n * 136 + mh + u * 8);
    }
}

// ---------------------------------------------------------------------------
// out projection -> d_out fp32: both operands pre-split, 4-slot rings,
// one sync per chunk. grid (8, 32), 512 thr
// ---------------------------------------------------------------------------
__global__ __launch_bounds__(512, 1) void k_out(float* __restrict__ out)
{
    PROJ_PROLOGUE();
    const int col0 = blockIdx.x * 128, row0 = blockIdx.y * 128;

    const int m_a = tid >> 2, kq = tid & 3;
    const int kb = tid >> 4, nq = tid & 15;
    const int LDBv = 1024;
    const u16* srcAH = g_pool + O_YH + (size_t)(row0 + m_a) * DMODEL + kq * 8;
    const u16* srcAL = g_pool + O_YL + (size_t)(row0 + m_a) * DMODEL + kq * 8;
    const u16* srcBH = g_pool + O_WOH + (size_t)kb * LDBv + col0 + nq * 8;
    const u16* srcBL = g_pool + O_WOL + (size_t)kb * LDBv + col0 + nq * 8;
    const uint32_t dAb = sb + m_a * 80 + kq * 16;
    const uint32_t dBb = sb + OUT_BBASE + kb * 272 + nq * 16;

    #define CPA_OUT(KCN, DAB)                                                 \
        {                                                                     \
            cpasync16((DAB),          srcAH + (size_t)(KCN) * 32);            \
            cpasync16((DAB) + OFF_AL, srcAL + (size_t)(KCN) * 32);            \
        }

    CPA_OUT(0, dAb + 0 * ABUF); CPB(0, dBb + 0 * BSTRIDE); CP_COMMIT();
    CPA_OUT(1, dAb + 1 * ABUF); CPB(1, dBb + 1 * BSTRIDE); CP_COMMIT();
    CPA_OUT(2, dAb + 2 * ABUF); CPB(2, dBb + 2 * BSTRIDE); CP_COMMIT();

    #pragma unroll 1
    for (int kc = 0; kc < 32; ++kc) {
        if (kc < 30) CP_WAIT(2); else if (kc == 30) CP_WAIT(1); else CP_WAIT(0);
        __syncthreads();
        if (kc <= 28) {
            CPA_OUT(kc + 3, dAb + ((kc + 3) & 3) * ABUF);
            CPB(kc + 3, dBb + ((kc + 3) & 3) * BSTRIDE);
            CP_COMMIT();
        }
        const uint32_t aB = sb + (kc & 3) * ABUF;
        const uint32_t bB = sb + OUT_BBASE + (kc & 3) * BSTRIDE;
        PROJ_MMA_PHASE(aB, OFF_AL, bB)
    }

    const int g = lane >> 2, tg = lane & 3;
    #pragma unroll
    for (int i = 0; i < 2; ++i) {
        int r = row0 + wm * 32 + i * 16 + g;
        #pragma unroll
        for (int j = 0; j < 4; ++j) {
            int c = col0 + wn * 32 + j * 8 + 2 * tg;
            float2 v0 = make_float2(acc[i][j][0] * 0.03125f, acc[i][j][1] * 0.03125f);
            float2 v1 = make_float2(acc[i][j][2] * 0.03125f, acc[i][j][3] * 0.03125f);
            *(float2*)(out + (size_t)r * DMODEL + c) = v0;
            *(float2*)(out + (size_t)(r + 8) * DMODEL + c) = v1;
        }
    }
}

// ---------------------------------------------------------------------------
// attention — UNCHANGED from the twice-proven R10/R12 kernel.
// grid (16 qt, 32 bh), 256 threads, warp w owns q-rows 16w..16w+15.
// ---------------------------------------------------------------------------
#define ATTN_SMEM 163840

__device__ __forceinline__ void attn_load_kv(uint32_t sbuf, int bh, int jt, int tid)
{
    {
        const int r = tid >> 1, cbx = (tid & 1) * 4;
        const size_t go = ((size_t)bh * LSEQ + jt * 128 + r) * DHEAD + cbx * 8;
        const uint32_t base = sbuf + r * 128;
        #pragma unroll
        for (int c = 0; c < 4; ++c) {
            uint32_t cc = ((uint32_t)(cbx + c) ^ (r & 7)) * 16;
            cpasync16(base + cc,         g_pool + O_KH + go + c * 8);
            cpasync16(base + 16384 + cc, g_pool + O_KL + go + c * 8);
        }
    }
    {
        const int r = tid >> 2, cbx = (tid & 3) * 4;
        const size_t go = ((size_t)bh * DHEAD + r) * LSEQ + jt * 128 + cbx * 8;
        const uint32_t base = sbuf + 32768 + r * 256;
        #pragma unroll
        for (int c = 0; c < 4; ++c) {
            uint32_t cc = ((uint32_t)(cbx + c) ^ ((r & 7) << 1)) * 16;
            cpasync16(base + cc,         g_pool + O_VTH + go + c * 8);
            cpasync16(base + 16384 + cc, g_pool + O_VTL + go + c * 8);
        }
    }
    CP_COMMIT();
}

__global__ __launch_bounds__(256, 1) void k_attn()
{
    extern __shared__ char smraw[];
    const uint32_t sb = smem_u32(smraw);
    const int qt = (int)gridDim.x - 1 - (int)blockIdx.x;
    const int bh = blockIdx.y;
    const int tid = threadIdx.x, lane = tid & 31, wid = tid >> 5;
    const int g = lane >> 2, tg = lane & 3;

    {
        const int r = tid >> 1, cbx = (tid & 1) * 4;
        const size_t go = ((size_t)bh * LSEQ + qt * 128 + r) * DHEAD + cbx * 8;
        const uint32_t base = sb + r * 128;
        #pragma unroll
        for (int c = 0; c < 4; ++c) {
            uint32_t cc = ((uint32_t)(cbx + c) ^ (r & 7)) * 16;
            cpasync16(base + cc,         g_pool + O_QH + go + c * 8);
            cpasync16(base + 16384 + cc, g_pool + O_QL + go + c * 8);
        }
        CP_COMMIT();
    }
    attn_load_kv(sb + 32768, bh, 0, tid);

    CP_WAIT(1);
    __syncthreads();

    uint32_t qh[4][4], ql[4][4];
    {
        int row = wid * 16 + (lane & 15);
        #pragma unroll
        for (int l = 0; l < 4; ++l) {
            int chunk = 2 * l + (lane >> 4);
            uint32_t a = sb + row * 128 + ((chunk ^ (row & 7)) * 16);
            LDSM4(qh[l][0], qh[l][1], qh[l][2], qh[l][3], a);
            LDSM4(ql[l][0], ql[l][1], ql[l][2], ql[l][3], a + 16384);
        }
    }

    float o[8][4];
    #pragma unroll
    for (int j = 0; j < 8; ++j)
        #pragma unroll
        for (int c = 0; c < 4; ++c) o[j][c] = 0.f;
    float den0 = 0.f, den1 = 0.f;

    const int rq = wid * 16 + g;

    int buf = 0;
    #pragma unroll 1
    for (int jt = 0; jt <= qt; ++jt) {
        if (jt < qt) { attn_load_kv(sb + 32768 + (buf ^ 1) * 65536, bh, jt + 1, tid); CP_WAIT(1); }
        else CP_WAIT(0);
        __syncthreads();
        const uint32_t sK = sb + 32768 + buf * 65536;
        const uint32_t sV = sK + 32768;

        const bool dg = (jt == qt);
        const int kkmax = dg ? wid : 7;

        #pragma unroll 1
        for (int kk = 0; kk <= kkmax; ++kk) {
            float s0[4] = {0.f, 0.f, 0.f, 0.f};
            float s1[4] = {0.f, 0.f, 0.f, 0.f};
            {
                int row = kk * 16 + (lane & 7) + ((lane >> 4) << 3);
                #pragma unroll
                for (int l = 0; l < 4; ++l) {
                    int chunk = 2 * l + ((lane >> 3) & 1);
                    uint32_t a = sK + row * 128 + ((chunk ^ (row & 7)) * 16);
                    uint32_t b0, b1, b2, b3, c0, c1, c2, c3;
                    LDSM4(b0, b1, b2, b3, a);
                    LDSM4(c0, c1, c2, c3, a + 16384);
                    MMA4(s0[0], s0[1], s0[2], s0[3], qh[l][0], qh[l][1], qh[l][2], qh[l][3], b0, b1);
                    MMA4(s0[0], s0[1], s0[2], s0[3], ql[l][0], ql[l][1], ql[l][2], ql[l][3], b0, b1);
                    MMA4(s0[0], s0[1], s0[2], s0[3], qh[l][0], qh[l][1], qh[l][2], qh[l][3], c0, c1);
                    MMA4(s1[0], s1[1], s1[2], s1[3], qh[l][0], qh[l][1], qh[l][2], qh[l][3], b2, b3);
                    MMA4(s1[0], s1[1], s1[2], s1[3], ql[l][0], ql[l][1], ql[l][2], ql[l][3], b2, b3);
                    MMA4(s1[0], s1[1], s1[2], s1[3], qh[l][0], qh[l][1], qh[l][2], qh[l][3], c2, c3);
                }
            }

            uint32_t p0, p1, p2, p3, r0, r1, r2, r3;
            {
                float e0 = fast_exp(s0[0] * 0.015625f);
                float e1 = fast_exp(s0[1] * 0.015625f);
                float e2 = fast_exp(s0[2] * 0.015625f);
                float e3 = fast_exp(s0[3] * 0.015625f);
                float f0 = fast_exp(s1[0] * 0.015625f);
                float f1 = fast_exp(s1[1] * 0.015625f);
                float f2 = fast_exp(s1[2] * 0.015625f);
                float f3 = fast_exp(s1[3] * 0.015625f);
                if (dg) {
                    int c0i = kk * 16 + 2 * tg;
                    if (c0i > rq)          e0 = 0.f;
                    if (c0i + 1 > rq)      e1 = 0.f;
                    if (c0i > rq + 8)      e2 = 0.f;
                    if (c0i + 1 > rq + 8)  e3 = 0.f;
                    if (c0i + 8 > rq)      f0 = 0.f;
                    if (c0i + 9 > rq)      f1 = 0.f;
                    if (c0i + 8 > rq + 8)  f2 = 0.f;
                    if (c0i + 9 > rq + 8)  f3 = 0.f;
                }
                den0 += e0 + e1 + f0 + f1;
                den1 += e2 + e3 + f2 + f3;
                float h0, l0, h1, l1;
                bsplit(e0, h0, l0); bsplit(e1, h1, l1);
                p0 = pack2(h0, h1); r0 = pack2(l0, l1);
                bsplit(e2, h0, l0); bsplit(e3, h1, l1);
                p1 = pack2(h0, h1); r1 = pack2(l0, l1);
                bsplit(f0, h0, l0); bsplit(f1, h1, l1);
                p2 = pack2(h0, h1); r2 = pack2(l0, l1);
                bsplit(f2, h0, l0); bsplit(f3, h1, l1);
                p3 = pack2(h0, h1); r3 = pack2(l0, l1);
            }

            {
                int row = (lane & 7) + ((lane >> 4) << 3);
                int chunk = 2 * kk + ((lane >> 3) & 1);
                #pragma unroll
                for (int np = 0; np < 4; ++np) {
                    int r2i = np * 16 + row;
                    uint32_t a = sV + r2i * 256 + ((chunk ^ ((r2i & 7) << 1)) * 16);
                    uint32_t vb0, vb1, vb2, vb3, vc0, vc1, vc2, vc3;
                    LDSM4(vb0, vb1, vb2, vb3, a);
                    LDSM4(vc0, vc1, vc2, vc3, a + 16384);
                    MMA4(o[2*np][0], o[2*np][1], o[2*np][2], o[2*np][3], p0, p1, p2, p3, vb0, vb1);
                    MMA4(o[2*np][0], o[2*np][1], o[2*np][2], o[2*np][3], r0, r1, r2, r3, vb0, vb1);
                    MMA4(o[2*np][0], o[2*np][1], o[2*np][2], o[2*np][3], p0, p1, p2, p3, vc0, vc1);
                    MMA4(o[2*np+1][0], o[2*np+1][1], o[2*np+1][2], o[2*np+1][3], p0, p1, p2, p3, vb2, vb3);
                    MMA4(o[2*np+1][0], o[2*np+1][1], o[2*np+1][2], o[2*np+1][3], r0, r1, r2, r3, vb2, vb3);
                    MMA4(o[2*np+1][0], o[2*np+1][1], o[2*np+1][2], o[2*np+1][3], p0, p1, p2, p3, vc2, vc3);
                }
            }
        }
        __syncthreads();
        buf ^= 1;
    }

    #pragma unroll
    for (int m = 1; m < 4; m <<= 1) {
        den0 += __shfl_xor_sync(0xffffffffu, den0, m);
        den1 += __shfl_xor_sync(0xffffffffu, den1, m);
    }
    const float inv0 = 1.f / den0, inv1 = 1.f / den1;

    const int b = bh >> 4, h = bh & 15;
    const size_t m0 = (size_t)b * LSEQ + qt * 128 + wid * 16 + g;
    u16* Yh = g_pool + O_YH;
    u16* Yl = g_pool + O_YL;
    #pragma unroll
    for (int j = 0; j < 8; ++j) {
        int d = j * 8 + 2 * tg;
        float h0, l0, h1, l1, h2, l2, h3, l3;
        bsplit(o[j][0] * inv0, h0, l0);
        bsplit(o[j][1] * inv0, h1, l1);
        bsplit(o[j][2] * inv1, h2, l2);
        bsplit(o[j][3] * inv1, h3, l3);
        *(uint32_t*)(Yh + m0 * DMODEL + h * 64 + d) = pack2(h0, h1);
        *(uint32_t*)(Yl + m0 * DMODEL + h * 64 + d) = pack2(l0, l1);
        *(uint32_t*)(Yh + (m0 + 8) * DMODEL + h * 64 + d) = pack2(h2, h3);
        *(uint32_t*)(Yl + (m0 + 8) * DMODEL + h * 64 + d) = pack2(l2, l3);
    }
}

// ---------------------------------------------------------------------------
extern "C" void kernel_launch(void* const* d_in, const int* in_sizes, int n_in,
                              void* d_out, int out_size)
{
    const float* X    = (const float*)d_in[0];
    const float* Wqk  = (const float*)d_in[1];
    const float* Wv   = (const float*)d_in[2];
    const float* Wout = (const float*)d_in[3];
    const float* qsc  = (const float*)d_in[4];
    const float* qbi  = (const float*)d_in[5];
    const float* ksc  = (const float*)d_in[6];
    const float* kbi  = (const float*)d_in[7];
    float* out = (float*)d_out;

    cudaFuncSetAttribute(k_qk_ln, cudaFuncAttributeMaxDynamicSharedMemorySize, PROJ_SMEM);
    cudaFuncSetAttribute(k_v,     cudaFuncAttributeMaxDynamicSharedMemorySize, KV_SMEM);
    cudaFuncSetAttribute(k_out,   cudaFuncAttributeMaxDynamicSharedMemorySize, KOUT_SMEM);
    cudaFuncSetAttribute(k_attn,  cudaFuncAttributeMaxDynamicSharedMemorySize, ATTN_SMEM);

    k_wsplit<<<2048, 256>>>(Wqk,  O_WQKH, O_WQKL, 2048 * 1024 / 4);
    k_wsplit<<<1024, 256>>>(Wv,   O_WVH,  O_WVL,  1024 * 1024 / 4);

    k_qk_ln<<<dim3(HEADS, MROWS / 128), 512, PROJ_SMEM>>>(X, qsc, qbi, ksc, kbi);
    k_v<<<dim3(8, MROWS / 128), 512, KV_SMEM>>>(X);
    k_attn<<<dim3(LSEQ / 128, BH), 256, ATTN_SMEM>>>();
    k_wsplit<<<1024, 256>>>(Wout, O_WOH, O_WOL, 1024 * 1024 / 4);
    k_out<<<dim3(8, MROWS / 128), 512, KOUT_SMEM>>>(out);
}